// round 14
// baseline (speedup 1.0000x reference)
#include <cuda_runtime.h>
#include <cuda_bf16.h>
#include <cstdint>
#include <math.h>

#define NROWS 8192
#define D     128
// alpha = sqrt((1/0.07) * log2(e))
#define ALPHA  4.539816f
#define CLIP2  14.4269504089f   // 10 * log2(e)

#define NT       64
#define NTILES   2080          // NT*(NT+1)/2
#define GRID     296           // exactly 2 CTAs/SM -> whole grid co-resident
#define ROWS_PER_CTA 28        // ceil(8192/296)
#define ROWPITCH 80            // 64B data + 16B pad (LDSM conflict-free)
#define CHUNKB   (128 * ROWPITCH)
#define A_BYTES  (4 * CHUNKB)
#define B_BYTES  (4 * CHUNKB)
#define SMEM_DYN_BYTES (A_BYTES + B_BYTES) // 81920

// ---------------- device scratch -------------------------------------------
__device__ __nv_bfloat16 g_f16[NROWS * D];
__device__ float g_pos[NROWS];
__device__ float g_neg[NROWS];
__device__ int   g_lab[NROWS];
__device__ unsigned g_cnt   = 0;   // barrier counter (restored to 0 each launch)
__device__ unsigned g_sense = 0;   // toggles twice per launch -> restored

// ---------------- helpers ---------------------------------------------------
__device__ __forceinline__ uint32_t smem_u32(const void* p) {
    return (uint32_t)__cvta_generic_to_shared(p);
}
__device__ __forceinline__ void cpasync16(uint32_t s, const void* g) {
    asm volatile("cp.async.cg.shared.global [%0], [%1], 16;" :: "r"(s), "l"(g));
}
__device__ __forceinline__ void cp_commit() {
    asm volatile("cp.async.commit_group;" ::: "memory");
}
template <int N>
__device__ __forceinline__ void cp_wait() {
    asm volatile("cp.async.wait_group %0;" :: "n"(N) : "memory");
}
__device__ __forceinline__ void ldmx4(uint32_t* r, uint32_t addr) {
    asm volatile("ldmatrix.sync.aligned.m8n8.x4.shared.b16 {%0,%1,%2,%3}, [%4];"
                 : "=r"(r[0]), "=r"(r[1]), "=r"(r[2]), "=r"(r[3]) : "r"(addr));
}
__device__ __forceinline__ void mma16816(float* c, const uint32_t* a, uint32_t b0, uint32_t b1) {
    asm volatile(
        "mma.sync.aligned.m16n8k16.row.col.f32.bf16.bf16.f32 "
        "{%0,%1,%2,%3}, {%4,%5,%6,%7}, {%8,%9}, {%0,%1,%2,%3};"
        : "+f"(c[0]), "+f"(c[1]), "+f"(c[2]), "+f"(c[3])
        : "r"(a[0]), "r"(a[1]), "r"(a[2]), "r"(a[3]), "r"(b0), "r"(b1));
}
__device__ __forceinline__ float ex2(float x) {
    float r;
    asm("ex2.approx.f32 %0, %1;" : "=f"(r) : "f"(x));
    return r;
}
__device__ __forceinline__ float lg2(float x) {
    float r;
    asm("lg2.approx.f32 %0, %1;" : "=f"(r) : "f"(x));
    return r;
}
__device__ __forceinline__ void decode_tile(int ti, int& i, int& j) {
    i = (int)floorf((129.0f - sqrtf(129.0f * 129.0f - 8.0f * (float)ti)) * 0.5f);
    while (i > 0 && ti < i * NT - i * (i - 1) / 2) --i;
    while (ti >= (i + 1) * NT - (i + 1) * i / 2) ++i;
    j = i + (ti - (i * NT - i * (i - 1) / 2));
}

// sense-reversing grid barrier; all GRID CTAs are co-resident (2/SM).
__device__ __forceinline__ void grid_barrier(int tid) {
    __syncthreads();
    __shared__ unsigned s_go;
    if (tid == 0) {
        __threadfence();
        unsigned s = atomicOr(&g_sense, 0u);
        if (atomicAdd(&g_cnt, 1u) == GRID - 1) {
            atomicExch(&g_cnt, 0u);
            __threadfence();
            atomicExch(&g_sense, s ^ 1u);
        } else {
            while (atomicOr(&g_sense, 0u) == s) { }
        }
        __threadfence();
        s_go = 1;
    }
    __syncthreads();
}

// ---------------------------------------------------------------------------
__device__ __forceinline__ void load_A(uint32_t Abase, int aR, int tid) {
    #pragma unroll
    for (int ch = 0; ch < 4; ch++) {
        const int col = ch * 32;
        #pragma unroll
        for (int it = 0; it < 2; it++) {
            int idx = tid + it * 256;
            int r   = idx >> 2;
            int c4  = idx & 3;
            cpasync16(Abase + ch * CHUNKB + r * ROWPITCH + c4 * 16,
                      (const char*)&g_f16[(aR + r) * D + col] + c4 * 16);
        }
    }
}
__device__ __forceinline__ void load_B_pair(uint32_t Bbase, int c0, int bR, int tid) {
    #pragma unroll
    for (int cc = 0; cc < 2; cc++) {
        const int ch  = c0 + cc;
        const int col = ch * 32;
        #pragma unroll
        for (int it = 0; it < 2; it++) {
            int idx = tid + it * 256;
            int r   = idx >> 2;
            int c4  = idx & 3;
            cpasync16(Bbase + ch * CHUNKB + r * ROWPITCH + c4 * 16,
                      (const char*)&g_f16[(bR + r) * D + col] + c4 * 16);
        }
    }
}

__global__ void __launch_bounds__(256, 2) fused_kernel(
    const float* __restrict__ feat,
    const int*   __restrict__ lab32,
    float*       __restrict__ out)
{
    extern __shared__ char dsm[];
    __shared__ int labA[2][128];
    __shared__ int labB[2][128];
    __shared__ int s_is64;
    __shared__ float s_loss[ROWS_PER_CTA];

    const uint32_t smBase = smem_u32(dsm);
    const uint32_t Abase  = smBase;
    const uint32_t Bbase  = smBase + A_BYTES;
    const int tid  = threadIdx.x;
    const int warp = tid >> 5;
    const int lane = tid & 31;
    const int cta  = blockIdx.x;

    // ============ phase 0: normalize slice + labels + zero accum ============
    if (tid == 0) {
        bool is64 = true;
        #pragma unroll 8
        for (int k = 0; k < 32; k++)
            if (lab32[2 * k + 1] != 0) { is64 = false; break; }
        s_is64 = is64 ? 1 : 0;
        if (cta == 0) out[0] = 0.0f;
    }
    __syncthreads();

    const int rowBase = cta * ROWS_PER_CTA;
    #pragma unroll
    for (int p = 0; p < 2; p++) {
        const int rl  = (tid >> 4) + p * 16;     // 0..31
        const int l16 = tid & 15;
        const int row = rowBase + rl;
        if (rl < ROWS_PER_CTA && row < NROWS) {
            float4 v0 = *(const float4*)&feat[row * D + l16 * 8];
            float4 v1 = *(const float4*)&feat[row * D + l16 * 8 + 4];
            float ss = v0.x * v0.x + v0.y * v0.y + v0.z * v0.z + v0.w * v0.w
                     + v1.x * v1.x + v1.y * v1.y + v1.z * v1.z + v1.w * v1.w;
            #pragma unroll
            for (int o = 8; o > 0; o >>= 1) ss += __shfl_xor_sync(0xffffffffu, ss, o);
            float inv = ALPHA / fmaxf(sqrtf(ss), 1e-8f);
            ushort h[8];
            h[0] = __bfloat16_as_ushort(__float2bfloat16_rn(v0.x * inv));
            h[1] = __bfloat16_as_ushort(__float2bfloat16_rn(v0.y * inv));
            h[2] = __bfloat16_as_ushort(__float2bfloat16_rn(v0.z * inv));
            h[3] = __bfloat16_as_ushort(__float2bfloat16_rn(v0.w * inv));
            h[4] = __bfloat16_as_ushort(__float2bfloat16_rn(v1.x * inv));
            h[5] = __bfloat16_as_ushort(__float2bfloat16_rn(v1.y * inv));
            h[6] = __bfloat16_as_ushort(__float2bfloat16_rn(v1.z * inv));
            h[7] = __bfloat16_as_ushort(__float2bfloat16_rn(v1.w * inv));
            uint4 pk;
            pk.x = h[0] | (uint32_t)h[1] << 16;
            pk.y = h[2] | (uint32_t)h[3] << 16;
            pk.z = h[4] | (uint32_t)h[5] << 16;
            pk.w = h[6] | (uint32_t)h[7] << 16;
            *(uint4*)&((ushort*)g_f16)[row * D + l16 * 8] = pk;
            if (l16 == 0) {
                g_pos[row] = 0.0f;
                g_neg[row] = 0.0f;
                g_lab[row] = s_is64 ? lab32[2 * row] : lab32[row];
            }
        }
    }

    grid_barrier(tid);

    // ============ phase 1: triangular tiles (R13 body) ============
    const int warpRow = warp >> 1;
    const int warpCol = warp & 1;
    const int g   = lane >> 2;
    const int tig = lane & 3;

    uint32_t aOff[2];
    #pragma unroll
    for (int mi = 0; mi < 2; mi++)
        aOff[mi] = (uint32_t)((warpRow * 32 + mi * 16 + (lane & 15)) * ROWPITCH
                              + ((lane >> 4) * 16));
    uint32_t bOff[4];
    #pragma unroll
    for (int nt = 0; nt < 4; nt++)
        bOff[nt] = (uint32_t)((warpCol * 64 + nt * 16 + (lane & 7) + ((lane & 16) ? 8 : 0))
                              * ROWPITCH + ((lane & 8) ? 16 : 0));

    const int cnt   = 7 + (cta < 8 ? 1 : 0);
    const int start = cta * 7 + min(cta, 8);

    int i, j;
    decode_tile(start, i, j);
    int aR = i * 128, bR = j * 128;

    load_A(Abase, aR, tid);
    cp_commit();
    load_B_pair(Bbase, 0, bR, tid);
    cp_commit();

    #pragma unroll 1
    for (int t = 0; t < cnt; t++) {
        const bool diag = (i == j);
        const bool hasNext = (t + 1 < cnt);
        int i_n = i, j_n = j + 1;
        if (j == NT - 1) { i_n = i + 1; j_n = i_n; }
        const bool iChange = hasNext && (i_n != i);
        const int bRn = j_n * 128;
        const int lb = t & 1;

        float acc[2][8][4];
        #pragma unroll
        for (int a = 0; a < 2; a++)
            #pragma unroll
            for (int b = 0; b < 8; b++)
                #pragma unroll
                for (int k = 0; k < 4; k++) acc[a][b][k] = 0.0f;

        #pragma unroll
        for (int half = 0; half < 2; half++) {
            cp_wait<0>();
            __syncthreads();

            if (half == 0 && tid < 128) {
                labA[lb][tid] = g_lab[aR + tid];
                labB[lb][tid] = g_lab[bR + tid];
            }

            if (half == 0)
                load_B_pair(Bbase, 2, bR, tid);
            else if (hasNext)
                load_B_pair(Bbase, 0, bRn, tid);
            cp_commit();

            #pragma unroll
            for (int cc = 0; cc < 2; cc++) {
                const int c = half * 2 + cc;
                const uint32_t aS = Abase + c * CHUNKB;
                const uint32_t bS = Bbase + c * CHUNKB;
                #pragma unroll
                for (int k16 = 0; k16 < 2; k16++) {
                    uint32_t a[2][4];
                    ldmx4(a[0], aS + aOff[0] + k16 * 32);
                    ldmx4(a[1], aS + aOff[1] + k16 * 32);
                    uint32_t b[4][4];
                    #pragma unroll
                    for (int nt = 0; nt < 4; nt++)
                        ldmx4(b[nt], bS + bOff[nt] + k16 * 32);
                    #pragma unroll
                    for (int mi = 0; mi < 2; mi++)
                        #pragma unroll
                        for (int n8 = 0; n8 < 8; n8++) {
                            const uint32_t* bf = b[n8 >> 1];
                            if (n8 & 1) mma16816(acc[mi][n8], a[mi], bf[2], bf[3]);
                            else        mma16816(acc[mi][n8], a[mi], bf[0], bf[1]);
                        }
                }
            }
        }

        if (iChange) {
            __syncthreads();
            load_A(Abase, i_n * 128, tid);
            cp_commit();
        }

        float colPos[16], colNeg[16];
        #pragma unroll
        for (int x = 0; x < 16; x++) { colPos[x] = 0.0f; colNeg[x] = 0.0f; }

        #pragma unroll
        for (int mi = 0; mi < 2; mi++) {
            #pragma unroll
            for (int h = 0; h < 2; h++) {
                const int rT   = warpRow * 32 + mi * 16 + h * 8 + g;
                const int lrow = labA[lb][rT];
                float rowPos = 0.0f, rowNeg = 0.0f;
                #pragma unroll
                for (int n8 = 0; n8 < 8; n8++) {
                    #pragma unroll
                    for (int e = 0; e < 2; e++) {
                        const int cT = warpCol * 64 + n8 * 8 + 2 * tig + e;
                        float exv = ex2(fminf(acc[mi][n8][h * 2 + e], CLIP2));
                        if (diag) exv = (rT == cT) ? 0.0f : exv;
                        bool m = (lrow == labB[lb][cT]);
                        rowNeg += exv;
                        rowPos += m ? exv : 0.0f;
                        if (!diag) {
                            colNeg[n8 * 2 + e] += exv;
                            colPos[n8 * 2 + e] += m ? exv : 0.0f;
                        }
                    }
                }
                #pragma unroll
                for (int o = 1; o < 4; o <<= 1) {
                    rowPos += __shfl_xor_sync(0xffffffffu, rowPos, o);
                    rowNeg += __shfl_xor_sync(0xffffffffu, rowNeg, o);
                }
                if (tig == 0) {
                    atomicAdd(&g_pos[aR + rT], rowPos);
                    atomicAdd(&g_neg[aR + rT], rowNeg);
                }
            }
        }

        if (!diag) {
            #pragma unroll
            for (int x = 0; x < 16; x++) {
                #pragma unroll
                for (int o = 4; o < 32; o <<= 1) {
                    colPos[x] += __shfl_xor_sync(0xffffffffu, colPos[x], o);
                    colNeg[x] += __shfl_xor_sync(0xffffffffu, colNeg[x], o);
                }
            }
            if (g == 0) {
                #pragma unroll
                for (int x = 0; x < 16; x++) {
                    const int cT = warpCol * 64 + (x >> 1) * 8 + 2 * tig + (x & 1);
                    atomicAdd(&g_pos[bR + cT], colPos[x]);
                    atomicAdd(&g_neg[bR + cT], colNeg[x]);
                }
            }
        }

        i = i_n; j = j_n; aR = i * 128; bR = j * 128;
    }

    cp_wait<0>();      // retire any outstanding prefetches before exit path
    grid_barrier(tid);

    // ============ phase 2: loss over own slice ============
    {
        if (tid < ROWS_PER_CTA) {
            const int row = rowBase + tid;
            float s = 0.0f;
            if (row < NROWS) {
                float p = fmaxf(g_pos[row], 1e-8f);
                float n = fmaxf(g_neg[row], 1e-8f);
                s = lg2(n) - lg2(p);
            }
            s_loss[tid] = s;
        }
        __syncthreads();
        if (tid == 0) {
            float tot = 0.0f;
            #pragma unroll
            for (int k = 0; k < ROWS_PER_CTA; k++) tot += s_loss[k];
            atomicAdd(out, tot * (0.69314718056f / (float)NROWS));
        }
    }
}

// ---------------------------------------------------------------------------
extern "C" void kernel_launch(void* const* d_in, const int* in_sizes, int n_in,
                              void* d_out, int out_size)
{
    const float* feat  = (const float*)d_in[0];
    const int*   lab32 = (const int*)d_in[1];
    float*       out   = (float*)d_out;

    static bool attr_set = false;
    if (!attr_set) {
        cudaFuncSetAttribute(fused_kernel, cudaFuncAttributeMaxDynamicSharedMemorySize,
                             SMEM_DYN_BYTES);
        attr_set = true;
    }

    fused_kernel<<<GRID, 256, SMEM_DYN_BYTES>>>(feat, lab32, out);
}

// round 15
// speedup vs baseline: 1.0401x; 1.0401x over previous
#include <cuda_runtime.h>
#include <cuda_bf16.h>
#include <cstdint>
#include <math.h>

#define NROWS 8192
#define D     128
#define ALPHA  4.539816f        // sqrt((1/0.07)*log2(e))
#define CLIP2  14.4269504089f   // 10*log2(e)

#define NTI      64             // row blocks of 128
#define NTJ      128            // col blocks of 64
#define NTILES   4160           // sum_i (128-2i)
#define GRID     444            // 3 persistent CTAs per SM
#define ROWPITCH 80
#define A_CHUNKB (128 * ROWPITCH)      // 10240
#define B_CHUNKB (64 * ROWPITCH)       // 5120
#define A_BYTES  (4 * A_CHUNKB)        // 40960
#define B_BYTES  (4 * B_CHUNKB)        // 20480
#define SMEM_DYN_BYTES (A_BYTES + B_BYTES)   // 61440

// ---------------- device scratch -------------------------------------------
__device__ __nv_bfloat16 g_f16[NROWS * D];
__device__ float g_pos[NROWS];
__device__ float g_neg[NROWS];
__device__ int   g_lab[NROWS];

// ---------------- helpers ---------------------------------------------------
__device__ __forceinline__ uint32_t smem_u32(const void* p) {
    return (uint32_t)__cvta_generic_to_shared(p);
}
__device__ __forceinline__ void cpasync16(uint32_t s, const void* g) {
    asm volatile("cp.async.cg.shared.global [%0], [%1], 16;" :: "r"(s), "l"(g));
}
__device__ __forceinline__ void cp_commit() {
    asm volatile("cp.async.commit_group;" ::: "memory");
}
template <int N>
__device__ __forceinline__ void cp_wait() {
    asm volatile("cp.async.wait_group %0;" :: "n"(N) : "memory");
}
__device__ __forceinline__ void ldmx4(uint32_t* r, uint32_t addr) {
    asm volatile("ldmatrix.sync.aligned.m8n8.x4.shared.b16 {%0,%1,%2,%3}, [%4];"
                 : "=r"(r[0]), "=r"(r[1]), "=r"(r[2]), "=r"(r[3]) : "r"(addr));
}
__device__ __forceinline__ void mma16816(float* c, const uint32_t* a, uint32_t b0, uint32_t b1) {
    asm volatile(
        "mma.sync.aligned.m16n8k16.row.col.f32.bf16.bf16.f32 "
        "{%0,%1,%2,%3}, {%4,%5,%6,%7}, {%8,%9}, {%0,%1,%2,%3};"
        : "+f"(c[0]), "+f"(c[1]), "+f"(c[2]), "+f"(c[3])
        : "r"(a[0]), "r"(a[1]), "r"(a[2]), "r"(a[3]), "r"(b0), "r"(b1));
}
__device__ __forceinline__ float ex2(float x) {
    float r; asm("ex2.approx.f32 %0, %1;" : "=f"(r) : "f"(x)); return r;
}
__device__ __forceinline__ float lg2(float x) {
    float r; asm("lg2.approx.f32 %0, %1;" : "=f"(r) : "f"(x)); return r;
}
// tile list: i-major, j from 2i..127; start_i = i*(129-i)
__device__ __forceinline__ void decode_tile(int ti, int& i, int& j) {
    i = (int)((129.0f - sqrtf(129.0f * 129.0f - 4.0f * (float)ti)) * 0.5f);
    while (i > 0 && ti < i * (129 - i)) --i;
    while (ti >= (i + 1) * (128 - i)) ++i;
    j = 2 * i + (ti - i * (129 - i));
}

// ---------------------------------------------------------------------------
// Kernel 1: normalize -> alpha-prescaled bf16 (R13 form); zeroes out[0].
// ---------------------------------------------------------------------------
__global__ void __launch_bounds__(512) normalize_kernel(
    const float* __restrict__ feat,
    const int*   __restrict__ lab32,
    float*       __restrict__ out)
{
    __shared__ int s_is64;
    const int tid  = threadIdx.x;
    const int sub  = tid >> 4;
    const int l16  = tid & 15;
    const int row  = blockIdx.x * 32 + sub;

    if (tid == 0) {
        bool is64 = true;
        #pragma unroll 8
        for (int k = 0; k < 32; k++)
            if (lab32[2 * k + 1] != 0) { is64 = false; break; }
        s_is64 = is64 ? 1 : 0;
        if (blockIdx.x == 0) out[0] = 0.0f;
    }

    float4 v0 = *(const float4*)&feat[row * D + l16 * 8];
    float4 v1 = *(const float4*)&feat[row * D + l16 * 8 + 4];
    float ss = v0.x * v0.x + v0.y * v0.y + v0.z * v0.z + v0.w * v0.w
             + v1.x * v1.x + v1.y * v1.y + v1.z * v1.z + v1.w * v1.w;
    #pragma unroll
    for (int o = 8; o > 0; o >>= 1) ss += __shfl_xor_sync(0xffffffffu, ss, o);
    float inv = ALPHA / fmaxf(sqrtf(ss), 1e-8f);

    ushort h[8];
    h[0] = __bfloat16_as_ushort(__float2bfloat16_rn(v0.x * inv));
    h[1] = __bfloat16_as_ushort(__float2bfloat16_rn(v0.y * inv));
    h[2] = __bfloat16_as_ushort(__float2bfloat16_rn(v0.z * inv));
    h[3] = __bfloat16_as_ushort(__float2bfloat16_rn(v0.w * inv));
    h[4] = __bfloat16_as_ushort(__float2bfloat16_rn(v1.x * inv));
    h[5] = __bfloat16_as_ushort(__float2bfloat16_rn(v1.y * inv));
    h[6] = __bfloat16_as_ushort(__float2bfloat16_rn(v1.z * inv));
    h[7] = __bfloat16_as_ushort(__float2bfloat16_rn(v1.w * inv));
    uint4 pk;
    pk.x = h[0] | (uint32_t)h[1] << 16;
    pk.y = h[2] | (uint32_t)h[3] << 16;
    pk.z = h[4] | (uint32_t)h[5] << 16;
    pk.w = h[6] | (uint32_t)h[7] << 16;
    *(uint4*)&((ushort*)g_f16)[row * D + l16 * 8] = pk;

    __syncthreads();
    if (l16 == 0) {
        g_pos[row] = 0.0f;
        g_neg[row] = 0.0f;
        g_lab[row] = s_is64 ? lab32[2 * row] : lab32[row];
    }
}

// ---------------------------------------------------------------------------
// Kernel 2: 128x64 tiles, 3 CTAs/SM. Resident A (128xK); B (64xK) streamed
// in 2-chunk pairs. Diag-band tiles (j==2i or 2i+1): full compute, row sums
// only; pure-upper tiles add column sums via symmetry.
// ---------------------------------------------------------------------------
__device__ __forceinline__ void load_A(uint32_t Abase, int aR, int tid) {
    #pragma unroll
    for (int ch = 0; ch < 4; ch++) {
        const int col = ch * 32;
        #pragma unroll
        for (int it = 0; it < 2; it++) {
            int idx = tid + it * 256;
            int r   = idx >> 2;
            int c4  = idx & 3;
            cpasync16(Abase + ch * A_CHUNKB + r * ROWPITCH + c4 * 16,
                      (const char*)&g_f16[(aR + r) * D + col] + c4 * 16);
        }
    }
}
__device__ __forceinline__ void load_B_pair(uint32_t Bbase, int c0, int bR, int tid) {
    #pragma unroll
    for (int cc = 0; cc < 2; cc++) {
        const int ch  = c0 + cc;
        const int col = ch * 32;
        int r  = tid >> 2;
        int c4 = tid & 3;
        cpasync16(Bbase + ch * B_CHUNKB + r * ROWPITCH + c4 * 16,
                  (const char*)&g_f16[(bR + r) * D + col] + c4 * 16);
    }
}

__global__ void __launch_bounds__(256, 3) sim_mma_kernel()
{
    extern __shared__ char dsm[];
    __shared__ int labA[2][128];
    __shared__ int labB[2][64];

    const uint32_t smBase = smem_u32(dsm);
    const uint32_t Abase  = smBase;
    const uint32_t Bbase  = smBase + A_BYTES;
    const int tid  = threadIdx.x;
    const int warp = tid >> 5;
    const int lane = tid & 31;
    const int warpRow = warp >> 1;   // 0..3 (32-row bands)
    const int warpCol = warp & 1;    // 0..1 (32-col bands)
    const int g   = lane >> 2;
    const int tig = lane & 3;

    uint32_t aOff[2];
    #pragma unroll
    for (int mi = 0; mi < 2; mi++)
        aOff[mi] = (uint32_t)((warpRow * 32 + mi * 16 + (lane & 15)) * ROWPITCH
                              + ((lane >> 4) * 16));
    uint32_t bOff[2];
    #pragma unroll
    for (int nt = 0; nt < 2; nt++)
        bOff[nt] = (uint32_t)((warpCol * 32 + nt * 16 + (lane & 7) + ((lane & 16) ? 8 : 0))
                              * ROWPITCH + ((lane & 8) ? 16 : 0));

    // contiguous runs: 4160 = 444*9 + 164
    const int cta   = blockIdx.x;
    const int cnt   = 9 + (cta < 164 ? 1 : 0);
    const int start = cta * 9 + min(cta, 164);

    int i, j;
    decode_tile(start, i, j);
    int aR = i * 128, bR = j * 64;

    load_A(Abase, aR, tid);
    cp_commit();
    load_B_pair(Bbase, 0, bR, tid);
    cp_commit();

    #pragma unroll 1
    for (int t = 0; t < cnt; t++) {
        const bool diag = (j >> 1) == i;          // j == 2i or 2i+1
        const bool hasNext = (t + 1 < cnt);
        int i_n = i, j_n = j + 1;
        if (j_n > 127) { i_n = i + 1; j_n = 2 * i_n; }
        const bool iChange = hasNext && (i_n != i);
        const int bRn = j_n * 64;
        const int lb = t & 1;

        float acc[2][4][4];
        #pragma unroll
        for (int a = 0; a < 2; a++)
            #pragma unroll
            for (int b = 0; b < 4; b++)
                #pragma unroll
                for (int k = 0; k < 4; k++) acc[a][b][k] = 0.0f;

        #pragma unroll
        for (int half = 0; half < 2; half++) {
            cp_wait<0>();
            __syncthreads();

            if (half == 0) {
                if (tid < 128) labA[lb][tid] = g_lab[aR + tid];
                else if (tid < 192) labB[lb][tid - 128] = g_lab[bR + tid - 128];
            }

            if (half == 0)
                load_B_pair(Bbase, 2, bR, tid);
            else if (hasNext)
                load_B_pair(Bbase, 0, bRn, tid);
            cp_commit();

            #pragma unroll
            for (int cc = 0; cc < 2; cc++) {
                const int c = half * 2 + cc;
                const uint32_t aS = Abase + c * A_CHUNKB;
                const uint32_t bS = Bbase + c * B_CHUNKB;
                #pragma unroll
                for (int k16 = 0; k16 < 2; k16++) {
                    uint32_t a[2][4];
                    ldmx4(a[0], aS + aOff[0] + k16 * 32);
                    ldmx4(a[1], aS + aOff[1] + k16 * 32);
                    uint32_t b[2][4];
                    ldmx4(b[0], bS + bOff[0] + k16 * 32);
                    ldmx4(b[1], bS + bOff[1] + k16 * 32);
                    #pragma unroll
                    for (int mi = 0; mi < 2; mi++)
                        #pragma unroll
                        for (int n8 = 0; n8 < 4; n8++) {
                            const uint32_t* bf = b[n8 >> 1];
                            if (n8 & 1) mma16816(acc[mi][n8], a[mi], bf[2], bf[3]);
                            else        mma16816(acc[mi][n8], a[mi], bf[0], bf[1]);
                        }
                }
            }
        }

        if (iChange) {
            __syncthreads();
            load_A(Abase, i_n * 128, tid);
            cp_commit();
        }

        // ---------------- fused epilogue ----------------
        float colPos[8], colNeg[8];
        #pragma unroll
        for (int x = 0; x < 8; x++) { colPos[x] = 0.0f; colNeg[x] = 0.0f; }

        #pragma unroll
        for (int mi = 0; mi < 2; mi++) {
            #pragma unroll
            for (int h = 0; h < 2; h++) {
                const int rT   = warpRow * 32 + mi * 16 + h * 8 + g;
                const int lrow = labA[lb][rT];
                float rowPos = 0.0f, rowNeg = 0.0f;
                #pragma unroll
                for (int n8 = 0; n8 < 4; n8++) {
                    #pragma unroll
                    for (int e = 0; e < 2; e++) {
                        const int cT = warpCol * 32 + n8 * 8 + 2 * tig + e;
                        float exv = ex2(fminf(acc[mi][n8][h * 2 + e], CLIP2));
                        if (diag) exv = (aR + rT == bR + cT) ? 0.0f : exv;
                        bool m = (lrow == labB[lb][cT]);
                        rowNeg += exv;
                        rowPos += m ? exv : 0.0f;
                        if (!diag) {
                            colNeg[n8 * 2 + e] += exv;
                            colPos[n8 * 2 + e] += m ? exv : 0.0f;
                        }
                    }
                }
                #pragma unroll
                for (int o = 1; o < 4; o <<= 1) {
                    rowPos += __shfl_xor_sync(0xffffffffu, rowPos, o);
                    rowNeg += __shfl_xor_sync(0xffffffffu, rowNeg, o);
                }
                if (tig == 0) {
                    atomicAdd(&g_pos[aR + rT], rowPos);
                    atomicAdd(&g_neg[aR + rT], rowNeg);
                }
            }
        }

        if (!diag) {
            #pragma unroll
            for (int x = 0; x < 8; x++) {
                #pragma unroll
                for (int o = 4; o < 32; o <<= 1) {
                    colPos[x] += __shfl_xor_sync(0xffffffffu, colPos[x], o);
                    colNeg[x] += __shfl_xor_sync(0xffffffffu, colNeg[x], o);
                }
            }
            if (g == 0) {
                #pragma unroll
                for (int x = 0; x < 8; x++) {
                    const int cT = warpCol * 32 + (x >> 1) * 8 + 2 * tig + (x & 1);
                    atomicAdd(&g_pos[bR + cT], colPos[x]);
                    atomicAdd(&g_neg[bR + cT], colNeg[x]);
                }
            }
        }

        i = i_n; j = j_n; aR = i * 128; bR = j * 64;
    }
}

// ---------------------------------------------------------------------------
// Kernel 3: loss reduction (R13 form).
// ---------------------------------------------------------------------------
__global__ void __launch_bounds__(256) loss_kernel(float* __restrict__ out)
{
    const int tid = threadIdx.x;
    const int idx = blockIdx.x * 256 + tid;
    float p = fmaxf(g_pos[idx], 1e-8f);
    float n = fmaxf(g_neg[idx], 1e-8f);
    float s = lg2(n) - lg2(p);
    #pragma unroll
    for (int o = 16; o > 0; o >>= 1) s += __shfl_xor_sync(0xffffffffu, s, o);
    __shared__ float red[8];
    if ((tid & 31) == 0) red[tid >> 5] = s;
    __syncthreads();
    if (tid == 0) {
        float tot = red[0] + red[1] + red[2] + red[3]
                  + red[4] + red[5] + red[6] + red[7];
        atomicAdd(out, tot * (0.69314718056f / (float)NROWS));
    }
}

// ---------------------------------------------------------------------------
extern "C" void kernel_launch(void* const* d_in, const int* in_sizes, int n_in,
                              void* d_out, int out_size)
{
    const float* feat  = (const float*)d_in[0];
    const int*   lab32 = (const int*)d_in[1];
    float*       out   = (float*)d_out;

    static bool attr_set = false;
    if (!attr_set) {
        cudaFuncSetAttribute(sim_mma_kernel, cudaFuncAttributeMaxDynamicSharedMemorySize,
                             SMEM_DYN_BYTES);
        attr_set = true;
    }

    normalize_kernel<<<NROWS / 32, 512>>>(feat, lab32, out);
    sim_mma_kernel<<<GRID, 256, SMEM_DYN_BYTES>>>();
    loss_kernel<<<NROWS / 256, 256>>>(out);
}

// round 16
// speedup vs baseline: 1.0962x; 1.0539x over previous
#include <cuda_runtime.h>
#include <cuda_bf16.h>
#include <cstdint>
#include <math.h>

#define NROWS 8192
#define D     128
#define ALPHA  4.539816f        // sqrt((1/0.07)*log2(e))
#define CLIP2  14.4269504089f   // 10*log2(e)

#define NT       64
#define NTILES   2080
#define GRID     296            // 2 persistent CTAs per SM
#define CHUNKB   8192           // 128 rows x 64B (one 32-elem K chunk, swizzled)
#define A_BYTES  (4 * CHUNKB)   // 32KB resident A
#define B_BYTES  (4 * CHUNKB)   // 32KB per B buffer
#define SMEM_DYN_BYTES (A_BYTES + 2 * B_BYTES)   // 98304

// ---------------- device scratch -------------------------------------------
__device__ __nv_bfloat16 g_f16[NROWS * D];
__device__ float g_pos[NROWS];
__device__ float g_neg[NROWS];
__device__ int   g_lab[NROWS];

// ---------------- helpers ---------------------------------------------------
__device__ __forceinline__ uint32_t smem_u32(const void* p) {
    return (uint32_t)__cvta_generic_to_shared(p);
}
__device__ __forceinline__ void cpasync16(uint32_t s, const void* g) {
    asm volatile("cp.async.cg.shared.global [%0], [%1], 16;" :: "r"(s), "l"(g));
}
__device__ __forceinline__ void cp_commit() {
    asm volatile("cp.async.commit_group;" ::: "memory");
}
template <int N>
__device__ __forceinline__ void cp_wait() {
    asm volatile("cp.async.wait_group %0;" :: "n"(N) : "memory");
}
__device__ __forceinline__ void ldmx4(uint32_t* r, uint32_t addr) {
    asm volatile("ldmatrix.sync.aligned.m8n8.x4.shared.b16 {%0,%1,%2,%3}, [%4];"
                 : "=r"(r[0]), "=r"(r[1]), "=r"(r[2]), "=r"(r[3]) : "r"(addr));
}
__device__ __forceinline__ void mma16816(float* c, const uint32_t* a, uint32_t b0, uint32_t b1) {
    asm volatile(
        "mma.sync.aligned.m16n8k16.row.col.f32.bf16.bf16.f32 "
        "{%0,%1,%2,%3}, {%4,%5,%6,%7}, {%8,%9}, {%0,%1,%2,%3};"
        : "+f"(c[0]), "+f"(c[1]), "+f"(c[2]), "+f"(c[3])
        : "r"(a[0]), "r"(a[1]), "r"(a[2]), "r"(a[3]), "r"(b0), "r"(b1));
}
__device__ __forceinline__ float ex2(float x) {
    float r; asm("ex2.approx.f32 %0, %1;" : "=f"(r) : "f"(x)); return r;
}
__device__ __forceinline__ float lg2(float x) {
    float r; asm("lg2.approx.f32 %0, %1;" : "=f"(r) : "f"(x)); return r;
}
__device__ __forceinline__ void decode_tile(int ti, int& i, int& j) {
    i = (int)floorf((129.0f - sqrtf(129.0f * 129.0f - 8.0f * (float)ti)) * 0.5f);
    while (i > 0 && ti < i * NT - i * (i - 1) / 2) --i;
    while (ti >= (i + 1) * NT - (i + 1) * i / 2) ++i;
    j = i + (ti - (i * NT - i * (i - 1) / 2));
}

// ---------------------------------------------------------------------------
// Kernel 1: normalize -> alpha-prescaled bf16; zeroes out[0]. (R13 form)
// ---------------------------------------------------------------------------
__global__ void __launch_bounds__(512) normalize_kernel(
    const float* __restrict__ feat,
    const int*   __restrict__ lab32,
    float*       __restrict__ out)
{
    __shared__ int s_is64;
    const int tid  = threadIdx.x;
    const int sub  = tid >> 4;
    const int l16  = tid & 15;
    const int row  = blockIdx.x * 32 + sub;

    if (tid == 0) {
        bool is64 = true;
        #pragma unroll 8
        for (int k = 0; k < 32; k++)
            if (lab32[2 * k + 1] != 0) { is64 = false; break; }
        s_is64 = is64 ? 1 : 0;
        if (blockIdx.x == 0) out[0] = 0.0f;
    }

    float4 v0 = *(const float4*)&feat[row * D + l16 * 8];
    float4 v1 = *(const float4*)&feat[row * D + l16 * 8 + 4];
    float ss = v0.x * v0.x + v0.y * v0.y + v0.z * v0.z + v0.w * v0.w
             + v1.x * v1.x + v1.y * v1.y + v1.z * v1.z + v1.w * v1.w;
    #pragma unroll
    for (int o = 8; o > 0; o >>= 1) ss += __shfl_xor_sync(0xffffffffu, ss, o);
    float inv = ALPHA / fmaxf(sqrtf(ss), 1e-8f);

    ushort h[8];
    h[0] = __bfloat16_as_ushort(__float2bfloat16_rn(v0.x * inv));
    h[1] = __bfloat16_as_ushort(__float2bfloat16_rn(v0.y * inv));
    h[2] = __bfloat16_as_ushort(__float2bfloat16_rn(v0.z * inv));
    h[3] = __bfloat16_as_ushort(__float2bfloat16_rn(v0.w * inv));
    h[4] = __bfloat16_as_ushort(__float2bfloat16_rn(v1.x * inv));
    h[5] = __bfloat16_as_ushort(__float2bfloat16_rn(v1.y * inv));
    h[6] = __bfloat16_as_ushort(__float2bfloat16_rn(v1.z * inv));
    h[7] = __bfloat16_as_ushort(__float2bfloat16_rn(v1.w * inv));
    uint4 pk;
    pk.x = h[0] | (uint32_t)h[1] << 16;
    pk.y = h[2] | (uint32_t)h[3] << 16;
    pk.z = h[4] | (uint32_t)h[5] << 16;
    pk.w = h[6] | (uint32_t)h[7] << 16;
    *(uint4*)&((ushort*)g_f16)[row * D + l16 * 8] = pk;

    __syncthreads();
    if (l16 == 0) {
        g_pos[row] = 0.0f;
        g_neg[row] = 0.0f;
        g_lab[row] = s_is64 ? lab32[2 * row] : lab32[row];
    }
}

// ---------------------------------------------------------------------------
// Kernel 2: R13 tile schedule; swizzled 64B-pitch smem; whole-tile B double
// buffer -> ONE cp wait per tile, prefetch issued before compute.
// swizzle: 16B sub-chunk s' = s ^ ((row>>1)&3); conflict-free LDSM + fills.
// ---------------------------------------------------------------------------
__device__ __forceinline__ void load_tile(uint32_t base, int rowBase, int tid) {
    #pragma unroll
    for (int ch = 0; ch < 4; ch++) {
        #pragma unroll
        for (int it = 0; it < 2; it++) {
            int idx = tid + it * 256;
            int r   = idx >> 2;
            int c4  = idx & 3;
            int sw  = c4 ^ ((r >> 1) & 3);
            cpasync16(base + ch * CHUNKB + r * 64 + sw * 16,
                      (const char*)&g_f16[(rowBase + r) * D + ch * 32] + c4 * 16);
        }
    }
}

__global__ void __launch_bounds__(256, 2) sim_mma_kernel()
{
    extern __shared__ char dsm[];
    __shared__ int labA[2][128];
    __shared__ int labB[2][128];

    const uint32_t smBase = smem_u32(dsm);
    const uint32_t Abase  = smBase;
    const uint32_t Bbase0 = smBase + A_BYTES;
    const int tid  = threadIdx.x;
    const int warp = tid >> 5;
    const int lane = tid & 31;
    const int warpRow = warp >> 1;
    const int warpCol = warp & 1;
    const int g   = lane >> 2;
    const int tig = lane & 3;

    // per-lane LDSM row bases + swizzle masks
    uint32_t aRowOff[2]; int aMask[2];
    #pragma unroll
    for (int mi = 0; mi < 2; mi++) {
        int rA = warpRow * 32 + mi * 16 + (lane & 15);
        aRowOff[mi] = (uint32_t)(rA * 64);
        aMask[mi]   = (rA >> 1) & 3;
    }
    const int sA0 = lane >> 4;
    uint32_t bRowOff[4]; int bMask[4];
    #pragma unroll
    for (int nt = 0; nt < 4; nt++) {
        int rB = warpCol * 64 + nt * 16 + (lane & 7) + ((lane & 16) ? 8 : 0);
        bRowOff[nt] = (uint32_t)(rB * 64);
        bMask[nt]   = (rB >> 1) & 3;
    }
    const int sB0 = (lane & 8) ? 1 : 0;

    const int cta   = blockIdx.x;
    const int cnt   = 7 + (cta < 8 ? 1 : 0);
    const int start = cta * 7 + min(cta, 8);

    int i, j;
    decode_tile(start, i, j);
    int aR = i * 128, bR = j * 128;

    // prologue: resident A + whole B tile 0 into buffer 0
    load_tile(Abase, aR, tid);
    load_tile(Bbase0, bR, tid);
    cp_commit();

    #pragma unroll 1
    for (int t = 0; t < cnt; t++) {
        const bool diag = (i == j);
        const bool hasNext = (t + 1 < cnt);
        int i_n = i, j_n = j + 1;
        if (j == NT - 1) { i_n = i + 1; j_n = i_n; }
        const bool iChange = hasNext && (i_n != i);
        const int bRn = j_n * 128;
        const int lb = t & 1;
        const uint32_t Bb = Bbase0 + (uint32_t)lb * B_BYTES;

        cp_wait<0>();
        __syncthreads();

        if (tid < 128) labA[lb][tid] = g_lab[aR + tid];
        else           labB[lb][tid - 128] = g_lab[bR + tid - 128];

        // prefetch next tile's whole B into the other buffer (covered by compute)
        if (hasNext)
            load_tile(Bbase0 + (uint32_t)(lb ^ 1) * B_BYTES, bRn, tid);
        cp_commit();

        float acc[2][8][4];
        #pragma unroll
        for (int a = 0; a < 2; a++)
            #pragma unroll
            for (int b = 0; b < 8; b++)
                #pragma unroll
                for (int k = 0; k < 4; k++) acc[a][b][k] = 0.0f;

        #pragma unroll
        for (int c = 0; c < 4; c++) {
            const uint32_t aS = Abase + c * CHUNKB;
            const uint32_t bS = Bb + c * CHUNKB;
            #pragma unroll
            for (int k16 = 0; k16 < 2; k16++) {
                uint32_t a[2][4];
                #pragma unroll
                for (int mi = 0; mi < 2; mi++)
                    ldmx4(a[mi], aS + aRowOff[mi]
                                  + (uint32_t)(((sA0 + 2 * k16) ^ aMask[mi]) << 4));
                uint32_t b[4][4];
                #pragma unroll
                for (int nt = 0; nt < 4; nt++)
                    ldmx4(b[nt], bS + bRowOff[nt]
                                  + (uint32_t)(((sB0 + 2 * k16) ^ bMask[nt]) << 4));
                #pragma unroll
                for (int mi = 0; mi < 2; mi++)
                    #pragma unroll
                    for (int n8 = 0; n8 < 8; n8++) {
                        const uint32_t* bf = b[n8 >> 1];
                        if (n8 & 1) mma16816(acc[mi][n8], a[mi], bf[2], bf[3]);
                        else        mma16816(acc[mi][n8], a[mi], bf[0], bf[1]);
                    }
            }
        }

        __syncthreads();   // labels visible; all warps done reading old A
        if (iChange) {
            load_tile(Abase, i_n * 128, tid);
            cp_commit();
        }

        // ---------------- fused epilogue (row + column sums) ----------------
        float colPos[16], colNeg[16];
        #pragma unroll
        for (int x = 0; x < 16; x++) { colPos[x] = 0.0f; colNeg[x] = 0.0f; }

        #pragma unroll
        for (int mi = 0; mi < 2; mi++) {
            #pragma unroll
            for (int h = 0; h < 2; h++) {
                const int rT   = warpRow * 32 + mi * 16 + h * 8 + g;
                const int lrow = labA[lb][rT];
                float rowPos = 0.0f, rowNeg = 0.0f;
                #pragma unroll
                for (int n8 = 0; n8 < 8; n8++) {
                    #pragma unroll
                    for (int e = 0; e < 2; e++) {
                        const int cT = warpCol * 64 + n8 * 8 + 2 * tig + e;
                        float exv = ex2(fminf(acc[mi][n8][h * 2 + e], CLIP2));
                        if (diag) exv = (rT == cT) ? 0.0f : exv;
                        bool m = (lrow == labB[lb][cT]);
                        rowNeg += exv;
                        rowPos += m ? exv : 0.0f;
                        if (!diag) {
                            colNeg[n8 * 2 + e] += exv;
                            colPos[n8 * 2 + e] += m ? exv : 0.0f;
                        }
                    }
                }
                #pragma unroll
                for (int o = 1; o < 4; o <<= 1) {
                    rowPos += __shfl_xor_sync(0xffffffffu, rowPos, o);
                    rowNeg += __shfl_xor_sync(0xffffffffu, rowNeg, o);
                }
                if (tig == 0) {
                    atomicAdd(&g_pos[aR + rT], rowPos);
                    atomicAdd(&g_neg[aR + rT], rowNeg);
                }
            }
        }

        if (!diag) {
            #pragma unroll
            for (int x = 0; x < 16; x++) {
                #pragma unroll
                for (int o = 4; o < 32; o <<= 1) {
                    colPos[x] += __shfl_xor_sync(0xffffffffu, colPos[x], o);
                    colNeg[x] += __shfl_xor_sync(0xffffffffu, colNeg[x], o);
                }
            }
            if (g == 0) {
                #pragma unroll
                for (int x = 0; x < 16; x++) {
                    const int cT = warpCol * 64 + (x >> 1) * 8 + 2 * tig + (x & 1);
                    atomicAdd(&g_pos[bR + cT], colPos[x]);
                    atomicAdd(&g_neg[bR + cT], colNeg[x]);
                }
            }
        }

        i = i_n; j = j_n; aR = i * 128; bR = j * 128;
    }
}

// ---------------------------------------------------------------------------
// Kernel 3: loss reduction (R13 form).
// ---------------------------------------------------------------------------
__global__ void __launch_bounds__(256) loss_kernel(float* __restrict__ out)
{
    const int tid = threadIdx.x;
    const int idx = blockIdx.x * 256 + tid;
    float p = fmaxf(g_pos[idx], 1e-8f);
    float n = fmaxf(g_neg[idx], 1e-8f);
    float s = lg2(n) - lg2(p);
    #pragma unroll
    for (int o = 16; o > 0; o >>= 1) s += __shfl_xor_sync(0xffffffffu, s, o);
    __shared__ float red[8];
    if ((tid & 31) == 0) red[tid >> 5] = s;
    __syncthreads();
    if (tid == 0) {
        float tot = red[0] + red[1] + red[2] + red[3]
                  + red[4] + red[5] + red[6] + red[7];
        atomicAdd(out, tot * (0.69314718056f / (float)NROWS));
    }
}

// ---------------------------------------------------------------------------
extern "C" void kernel_launch(void* const* d_in, const int* in_sizes, int n_in,
                              void* d_out, int out_size)
{
    const float* feat  = (const float*)d_in[0];
    const int*   lab32 = (const int*)d_in[1];
    float*       out   = (float*)d_out;

    static bool attr_set = false;
    if (!attr_set) {
        cudaFuncSetAttribute(sim_mma_kernel, cudaFuncAttributeMaxDynamicSharedMemorySize,
                             SMEM_DYN_BYTES);
        attr_set = true;
    }

    normalize_kernel<<<NROWS / 32, 512>>>(feat, lab32, out);
    sim_mma_kernel<<<GRID, 256, SMEM_DYN_BYTES>>>();
    loss_kernel<<<NROWS / 256, 256>>>(out);
}